// round 14
// baseline (speedup 1.0000x reference)
#include <cuda_runtime.h>

#define BB 2
#define CC 128
#define HH 128
#define WWD 128
#define HW 16384
#define GG 8
#define CG 16
#define KK9 9
#define OMC 216
#define KDIM 1152
#define KC 16

typedef unsigned long long ull;

// ---------------- static scratch ----------------
__device__ float g_feat_up [BB*CC*HW];
__device__ float g_feat_arm[BB*CC*HW];
__device__ float g_offf    [BB*CC*HW];
__device__ float g_om      [BB*OMC*HW];
__device__ float g_pooled  [BB*CC];
__device__ float g_scale   [BB*CC];
// duplicated (f32x2) weight layouts: each element is (w,w) packed in 64 bits
__device__ ull g_WD_fsm [BB*CC*CC];     // [b][c][o], scale folded
__device__ ull g_WD_off [2*CC*CC];      // [c][o], x2 folded for c>=128
__device__ ull g_WD_om  [KDIM*256];     // [tap*128+c][o pad 256]
__device__ ull g_WD_dcn [KDIM*CC];      // [(g*9+kk)*16+cg][o]

// ---------------- helpers ----------------
__device__ __forceinline__ ull ffma2(ull a, ull b, ull c){
    ull d;
    asm("fma.rn.f32x2 %0, %1, %2, %3;" : "=l"(d) : "l"(a), "l"(b), "l"(c));
    return d;
}
__device__ __forceinline__ ull splat2(float a){
    ull d;
    asm("mov.b64 %0, {%1, %1};" : "=l"(d) : "f"(a));
    return d;
}
__device__ __forceinline__ float2 unpack2(ull v){
    float2 r;
    asm("mov.b64 {%0, %1}, %2;" : "=f"(r.x), "=f"(r.y) : "l"(v));
    return r;
}
__device__ __forceinline__ int swz(int b){ return b ^ ((b >> 3) & 16); }
// W-row (1024B) position swizzle, keyed by 64B-segment index s (= tp at store,
// = to at load): chunk q in {0,1,2,3} of 16B each.
__device__ __forceinline__ int wsw(int s, int q){
    return s*64 + ((q*16) ^ (((s >> 1) & 3) << 4));
}

__device__ __forceinline__ unsigned su32(const void* p){
    return (unsigned)__cvta_generic_to_shared(p);
}
__device__ __forceinline__ void cp16(unsigned s, const void* g){
    asm volatile("cp.async.cg.shared.global [%0], [%1], 16;" :: "r"(s), "l"(g));
}
#define CP_COMMIT asm volatile("cp.async.commit_group;")
#define CP_WAIT0  asm volatile("cp.async.wait_group 0;")

// ---------------- inner MMA: 128o x 128p, K-chunk 16 ------------------------
// Ws: 16 rows x 1024B, dup-f32x2, wsw-swizzled. Xs: 16 rows x 512B, swz-swizzled.
__device__ __forceinline__ void mma_chunk(const char* __restrict__ Ws,
                                          const char* __restrict__ Xs,
                                          ull acc[8][4],
                                          int aO0, int aO1, int aO2, int aO3,
                                          int oB0, int oB1){
#pragma unroll
    for (int k = 0; k < KC; k++){
        const char* wr = Ws + k*1024;
        ulonglong2 a01 = *reinterpret_cast<const ulonglong2*>(wr + aO0);
        ulonglong2 a23 = *reinterpret_cast<const ulonglong2*>(wr + aO1);
        ulonglong2 a45 = *reinterpret_cast<const ulonglong2*>(wr + aO2);
        ulonglong2 a67 = *reinterpret_cast<const ulonglong2*>(wr + aO3);
        ulonglong2 b01 = *reinterpret_cast<const ulonglong2*>(Xs + k*512 + oB0);
        ulonglong2 b23 = *reinterpret_cast<const ulonglong2*>(Xs + k*512 + oB1);
        ull av[8] = {a01.x, a01.y, a23.x, a23.y, a45.x, a45.y, a67.x, a67.y};
#pragma unroll
        for (int j = 0; j < 8; j++){
            acc[j][0] = ffma2(av[j], b01.x, acc[j][0]);
            acc[j][1] = ffma2(av[j], b01.y, acc[j][1]);
            acc[j][2] = ffma2(av[j], b23.x, acc[j][2]);
            acc[j][3] = ffma2(av[j], b23.y, acc[j][3]);
        }
    }
}

// stage one W chunk (16 rows x 128 o, dup) via cp.async: 4x16B per thread
__device__ __forceinline__ void stageW(void* Wbuf, const ull* __restrict__ src_row,
                                       int r, int tp){
    unsigned wd = su32((char*)Wbuf + r*1024);
    const char* s = (const char*)(src_row + tp*8);
#pragma unroll
    for (int q = 0; q < 4; q++)
        cp16(wd + wsw(tp, q), s + q*16);
}

// ---------------- weight transposes (duplicated outputs) ----------------
__global__ void k_T_fsm2(const float* __restrict__ w){   // needs g_scale
    int i = blockIdx.x*256 + threadIdx.x;                // dst [b][c][o]
    if (i < BB*CC*CC){
        int b = i >> 14, c = (i >> 7) & 127, o = i & 127;
        g_WD_fsm[i] = splat2(w[o*CC + c] * g_scale[b*CC + c]);
    }
}
__global__ void k_T_off(const float* __restrict__ w){    // w: [128][256]
    int i = blockIdx.x*256 + threadIdx.x;                // dst [c][o]
    if (i < 2*CC*CC){
        int c = i >> 7, o = i & 127;
        float f = (c < CC) ? 1.f : 2.f;
        g_WD_off[i] = splat2(w[o*2*CC + c] * f);
    }
}
__global__ void k_T_om(const float* __restrict__ w){     // w: [216][128][3][3]
    int i = blockIdx.x*256 + threadIdx.x;
    if (i < KDIM*256){
        int o = i & 255, kidx = i >> 8;
        int tap = kidx >> 7, c = kidx & 127;
        g_WD_om[i] = splat2((o < OMC) ? w[(o*CC + c)*KK9 + tap] : 0.f);
    }
}
__global__ void k_T_dcn(const float* __restrict__ w){    // w: [128][128][3][3]
    int i = blockIdx.x*256 + threadIdx.x;
    if (i < KDIM*CC){
        int o = i & 127, kidx = i >> 7;
        int gk = kidx >> 4, cg = kidx & 15;
        int g = gk/9, kk = gk - g*9;
        int c = g*CG + cg;
        g_WD_dcn[i] = splat2(w[(o*CC + c)*KK9 + kk]);
    }
}

// ---------------- pooled mean + attention scale ----------------
__global__ void k_pool(const float* __restrict__ fl){
    int bc = blockIdx.x, t = threadIdx.x;
    const float* p = fl + bc*HW;
    float s = 0.f;
    for (int i = t; i < HW; i += 256) s += p[i];
    __shared__ float red[256];
    red[t] = s; __syncthreads();
#pragma unroll
    for (int o = 128; o > 0; o >>= 1){
        if (t < o) red[t] += red[t + o];
        __syncthreads();
    }
    if (t == 0) g_pooled[bc] = red[0] * (1.f/(float)HW);
}
__global__ void k_atten(const float* __restrict__ w_atten){
    int b = blockIdx.x, o = threadIdx.x;
    __shared__ float pl[CC];
    pl[o] = g_pooled[b*CC + o];
    __syncthreads();
    float s = 0.f;
    const float* wr = w_atten + o*CC;
    for (int c = 0; c < CC; c++) s = fmaf(pl[c], wr[c], s);
    s = fmaxf(s, 0.f);
    g_scale[b*CC + o] = 1.f + 1.f/(1.f + __expf(-s));
}

// ---------------- bilinear upsample ----------------
__global__ void k_upsample(const float* __restrict__ fs){
    int idx = blockIdx.x*256 + threadIdx.x;
    int x = idx & 127, y = (idx >> 7) & 127, bc = idx >> 14;
    float fy = y*0.5f - 0.25f, fx = x*0.5f - 0.25f;
    float y0f = floorf(fy), x0f = floorf(fx);
    float wy = fy - y0f, wx = fx - x0f;
    int y0 = (int)y0f, x0 = (int)x0f;
    int y0c = max(y0, 0), y1c = min(y0 + 1, 63);
    int x0c = max(x0, 0), x1c = min(x0 + 1, 63);
    const float* s = fs + bc*4096;
    float v00 = s[y0c*64 + x0c], v01 = s[y0c*64 + x1c];
    float v10 = s[y1c*64 + x0c], v11 = s[y1c*64 + x1c];
    g_feat_up[idx] = (1.f-wy)*((1.f-wx)*v00 + wx*v01) + wy*((1.f-wx)*v10 + wx*v11);
}

// ---------------- GEMM 1: feat_arm = relu(Wfsm' @ feat_l) ----------------
__global__ __launch_bounds__(256,2) void k_gemm_fsm(const float* __restrict__ feat_l){
    __shared__ ull  Wsm[2][KC*128];           // 2 x 16KB
    __shared__ float Xsm[2][KC*128];          // 2 x 8KB
    int y = blockIdx.x, b = blockIdx.y, t = threadIdx.x;
    int to = t >> 4, tp = t & 15, r = to;
    int oB0 = swz(tp*32), oB1 = swz(tp*32 + 16);
    int aO0 = wsw(to,0), aO1 = wsw(to,1), aO2 = wsw(to,2), aO3 = wsw(to,3);
    ull acc[8][4];
#pragma unroll
    for (int j = 0; j < 8; j++) for (int i = 0; i < 4; i++) acc[j][i] = 0ull;

    const ull*   wbase = g_WD_fsm + b*CC*CC + r*128;
    const float* xbase = feat_l + ((b*CC + r)*HH + y)*WWD + tp*8;

    auto stage = [&](int c){
        int buf = c & 1;
        stageW(Wsm[buf], wbase + c*KC*128, r, tp);
        unsigned xd = su32((char*)Xsm[buf] + r*512);
        cp16(xd + oB0, xbase + c*KC*HW);
        cp16(xd + oB1, xbase + c*KC*HW + 4);
        CP_COMMIT;
    };
    stage(0);
#pragma unroll 1
    for (int c = 0; c < 8; c++){
        CP_WAIT0;
        __syncthreads();
        if (c < 7) stage(c+1);
        mma_chunk((char*)Wsm[c&1], (char*)Xsm[c&1], acc, aO0, aO1, aO2, aO3, oB0, oB1);
    }
#pragma unroll
    for (int j = 0; j < 8; j++){
        int o = to*8 + j;
        float2* dst = reinterpret_cast<float2*>(g_feat_arm + ((b*CC+o)*HH + y)*WWD + tp*8);
#pragma unroll
        for (int i2 = 0; i2 < 4; i2++){
            float2 v = unpack2(acc[j][i2]);
            v.x = fmaxf(v.x, 0.f); v.y = fmaxf(v.y, 0.f);
            dst[i2] = v;
        }
    }
}

// ---------------- GEMM 2: offset_feat = relu(Woff' @ [feat_arm ; feat_up]) --
__global__ __launch_bounds__(256,2) void k_gemm_off(){
    __shared__ ull  Wsm[2][KC*128];
    __shared__ float Xsm[2][KC*128];
    int y = blockIdx.x, b = blockIdx.y, t = threadIdx.x;
    int to = t >> 4, tp = t & 15, r = to;
    int oB0 = swz(tp*32), oB1 = swz(tp*32 + 16);
    int aO0 = wsw(to,0), aO1 = wsw(to,1), aO2 = wsw(to,2), aO3 = wsw(to,3);
    ull acc[8][4];
#pragma unroll
    for (int j = 0; j < 8; j++) for (int i = 0; i < 4; i++) acc[j][i] = 0ull;

    const ull* wbase = g_WD_off + r*128;
    auto stage = [&](int c){
        int buf = c & 1;
        stageW(Wsm[buf], wbase + c*KC*128, r, tp);
        int ch = c*KC + r;
        const float* xp = (ch < CC) ? g_feat_arm + ((b*CC + ch)*HH + y)*WWD + tp*8
                                    : g_feat_up  + ((b*CC + ch - CC)*HH + y)*WWD + tp*8;
        unsigned xd = su32((char*)Xsm[buf] + r*512);
        cp16(xd + oB0, xp);
        cp16(xd + oB1, xp + 4);
        CP_COMMIT;
    };
    stage(0);
#pragma unroll 1
    for (int c = 0; c < 16; c++){
        CP_WAIT0;
        __syncthreads();
        if (c < 15) stage(c+1);
        mma_chunk((char*)Wsm[c&1], (char*)Xsm[c&1], acc, aO0, aO1, aO2, aO3, oB0, oB1);
    }
#pragma unroll
    for (int j = 0; j < 8; j++){
        int o = to*8 + j;
        float2* dst = reinterpret_cast<float2*>(g_offf + ((b*CC+o)*HH + y)*WWD + tp*8);
#pragma unroll
        for (int i2 = 0; i2 < 4; i2++){
            float2 v = unpack2(acc[j][i2]);
            v.x = fmaxf(v.x, 0.f); v.y = fmaxf(v.y, 0.f);
            dst[i2] = v;
        }
    }
}

// ---------------- GEMM 3: conv_offset_mask (implicit shifted GEMM) ----------
__global__ __launch_bounds__(256,2) void k_gemm_om(const float* __restrict__ b_offmask){
    __shared__ ull  Wsm[2][KC*128];
    __shared__ float Xsm[2][KC*128];
    int y = blockIdx.x, b = blockIdx.y, t = threadIdx.x;
    int o0 = blockIdx.z * 128;
    int to = t >> 4, tp = t & 15, r = to;
    int oB0 = swz(tp*32), oB1 = swz(tp*32 + 16);
    int aO0 = wsw(to,0), aO1 = wsw(to,1), aO2 = wsw(to,2), aO3 = wsw(to,3);
    bool act = (o0 + to*8) < OMC;        // skip padded outputs (slab 2)
    ull acc[8][4];
#pragma unroll
    for (int j = 0; j < 8; j++) for (int i = 0; i < 4; i++) acc[j][i] = 0ull;

    auto stW = [&](int c){
        int buf = c & 1;
        stageW(Wsm[buf], g_WD_om + (c*KC + r)*256 + o0, r, tp);
        CP_COMMIT;
    };
    float rx[8];
    auto prefX = [&](int c){
        int tap = c >> 3;
        int ty = tap/3 - 1, tx = tap - (tap/3)*3 - 1;
        int ch = (c & 7)*16 + r;
        int gy = y + ty;
        bool rowok = (gy >= 0) && (gy < HH);
        const float* rowp = g_offf + ((b*CC + ch)*HH + gy)*WWD;
#pragma unroll
        for (int i = 0; i < 8; i++){
            int gx = tp*8 + i + tx;
            rx[i] = (rowok && gx >= 0 && gx < WWD) ? rowp[gx] : 0.f;
        }
    };
    stW(0);
    prefX(0);
#pragma unroll 1
    for (int c = 0; c < 72; c++){
        int buf = c & 1;
        char* X = (char*)Xsm[buf] + r*512;
        *(float4*)(X + oB0) = make_float4(rx[0], rx[1], rx[2], rx[3]);
        *(float4*)(X + oB1) = make_float4(rx[4], rx[5], rx[6], rx[7]);
        CP_WAIT0;
        __syncthreads();
        if (c < 71){ stW(c+1); prefX(c+1); }
        if (act) mma_chunk((char*)Wsm[buf], (char*)Xsm[buf], acc, aO0, aO1, aO2, aO3, oB0, oB1);
    }
#pragma unroll
    for (int j = 0; j < 8; j++){
        int o = o0 + to*8 + j;
        if (o < OMC){
            float bias = b_offmask[o];
            float2* dst = reinterpret_cast<float2*>(g_om + (b*OMC + o)*HW + y*WWD + tp*8);
#pragma unroll
            for (int i2 = 0; i2 < 4; i2++){
                float2 v = unpack2(acc[j][i2]);
                v.x += bias; v.y += bias;
                dst[i2] = v;
            }
        }
    }
}

// ---------------- GEMM 4: modulated deformable conv + relu + residual -------
// dynamic smem: [0,32K) Wsm dup x2 | [32K,48K) Xsm x2 | [48K,52K) swt x2 | [52K,56K) sof x2
#define DCN_SMEM (32768 + 16384 + 4096 + 4096)
__global__ __launch_bounds__(256,2) void k_gemm_dcn(const float* __restrict__ feat_l,
                                                    const float* __restrict__ b_dcn,
                                                    float* __restrict__ out){
    extern __shared__ char dyn[];
    ull*    Wsm0 = (ull*)dyn;
    ull*    Wsm1 = (ull*)(dyn + 16384);
    float*  Xsm0 = (float*)(dyn + 32768);
    float*  Xsm1 = (float*)(dyn + 40960);
    float4* swt0 = (float4*)(dyn + 49152);
    float4* swt1 = (float4*)(dyn + 51200);
    int4*   sof0 = (int4*)(dyn + 53248);
    int4*   sof1 = (int4*)(dyn + 55296);
    ull*    Wb[2]  = {Wsm0, Wsm1};
    float*  Xb[2]  = {Xsm0, Xsm1};
    float4* swt[2] = {swt0, swt1};
    int4*   sof[2] = {sof0, sof1};

    int y = blockIdx.x, b = blockIdx.y, t = threadIdx.x;
    int to = t >> 4, tp = t & 15, r = to;
    int oB0 = swz(tp*32), oB1 = swz(tp*32 + 16);
    int aO0 = wsw(to,0), aO1 = wsw(to,1), aO2 = wsw(to,2), aO3 = wsw(to,3);
    ull acc[8][4];
#pragma unroll
    for (int j = 0; j < 8; j++) for (int i = 0; i < 4; i++) acc[j][i] = 0ull;

    int xs_self = t ^ ((t >> 3) & 7);
    const float* omp = g_om + b*OMC*HW + y*WWD + (t & 127);

    float rom0 = 0.f, rom1 = 0.f, rom2 = 0.f;
    auto load_rom = [&](int m){
        int g = m/9, kk = m - 9*g;
        rom0 = omp[(g*18 + kk*2    )*HW];
        rom1 = omp[(g*18 + kk*2 + 1)*HW];
        rom2 = omp[(144 + g*9 + kk )*HW];
    };
    auto calc_params = [&](int m, int pbuf){
        int kk = m - 9*(m/9);
        int x = t;
        float mval = 1.f/(1.f + __expf(-rom2));
        float py = (float)(y + kk/3 - 1) + rom0;
        float px = (float)(x + (kk - (kk/3)*3) - 1) + rom1;
        float y0f = floorf(py), x0f = floorf(px);
        float ly = py - y0f, lx = px - x0f;
        int y0 = (int)y0f, x0 = (int)x0f;
        float vy0 = (y0 >=  0 && y0 < HH    ) ? 1.f : 0.f;
        float vy1 = (y0 >= -1 && y0 < HH - 1) ? 1.f : 0.f;
        float vx0 = (x0 >=  0 && x0 < WWD    ) ? 1.f : 0.f;
        float vx1 = (x0 >= -1 && x0 < WWD - 1) ? 1.f : 0.f;
        float omy = 1.f - ly, omx = 1.f - lx;
        float4 w;
        w.x = omy*omx*vy0*vx0*mval;
        w.y = omy*lx *vy0*vx1*mval;
        w.z = ly *omx*vy1*vx0*mval;
        w.w = ly *lx *vy1*vx1*mval;
        int y0c = min(max(y0,0),HH-1),   y1c = min(max(y0+1,0),HH-1);
        int x0c = min(max(x0,0),WWD-1),  x1c = min(max(x0+1,0),WWD-1);
        sof[pbuf][xs_self] = make_int4(y0c*WWD + x0c, y0c*WWD + x1c,
                                       y1c*WWD + x0c, y1c*WWD + x1c);
        swt[pbuf][xs_self] = w;
    };
    auto stW = [&](int m){
        stageW(Wb[m & 1], g_WD_dcn + (m*16 + r)*128, r, tp);
        CP_COMMIT;
    };
    float rx[8];
    auto gather = [&](int m, int pbuf){
        int g = m/9;
        const float* fp = g_feat_up + (b*CC + g*CG + r)*HW;
#pragma unroll
        for (int i = 0; i < 8; i++){
            int px = tp*8 + i;
            int pidx = px ^ ((px >> 3) & 7);
            int4  o4 = sof[pbuf][pidx];
            float4 w4 = swt[pbuf][pidx];
            rx[i] = w4.x*fp[o4.x] + w4.y*fp[o4.y] + w4.z*fp[o4.z] + w4.w*fp[o4.w];
        }
    };

    if (t < 128){
        load_rom(0);
        calc_params(0, 0);
        load_rom(1);
    }
    stW(0);
    __syncthreads();
    gather(0, 0);

#pragma unroll 1
    for (int c = 0; c < 72; c++){
        int buf = c & 1;
        char* X = (char*)Xb[buf] + r*512;
        *(float4*)(X + oB0) = make_float4(rx[0], rx[1], rx[2], rx[3]);
        *(float4*)(X + oB1) = make_float4(rx[4], rx[5], rx[6], rx[7]);
        CP_WAIT0;
        __syncthreads();                              // X(c), W(c) ready
        if (c + 1 < 72){
            stW(c+1);
            if (t < 128) calc_params(c+1, (c+1) & 1);
            if (t < 128 && c + 2 < 72) load_rom(c+2);
        }
        __syncthreads();                              // params(c+1) ready
        if (c + 1 < 72) gather(c+1, (c+1) & 1);
        mma_chunk((char*)Wb[buf], (char*)Xb[buf], acc, aO0, aO1, aO2, aO3, oB0, oB1);
    }

#pragma unroll
    for (int j = 0; j < 8; j++){
        int o = to*8 + j;
        float bias = b_dcn[o];
        int base = ((b*CC + o)*HH + y)*WWD + tp*8;
        const float2* flp = reinterpret_cast<const float2*>(feat_l + base);
        float2* dst = reinterpret_cast<float2*>(out + base);
#pragma unroll
        for (int i2 = 0; i2 < 4; i2++){
            float2 v  = unpack2(acc[j][i2]);
            float2 fl = flp[i2];
            v.x = fmaxf(v.x + bias, 0.f) + fl.x;
            v.y = fmaxf(v.y + bias, 0.f) + fl.y;
            dst[i2] = v;
        }
    }
}

// ---------------- launcher ----------------
extern "C" void kernel_launch(void* const* d_in, const int* in_sizes, int n_in,
                              void* d_out, int out_size){
    (void)in_sizes; (void)n_in; (void)out_size;
    const float* feat_l    = (const float*)d_in[0];
    const float* feat_s    = (const float*)d_in[1];
    const float* w_atten   = (const float*)d_in[2];
    const float* w_fsm     = (const float*)d_in[3];
    const float* w_off     = (const float*)d_in[4];
    const float* w_offmask = (const float*)d_in[5];
    const float* b_offmask = (const float*)d_in[6];
    const float* w_dcn     = (const float*)d_in[7];
    const float* b_dcn     = (const float*)d_in[8];
    float* out = (float*)d_out;

    static bool attr_done = false;
    if (!attr_done){
        cudaFuncSetAttribute(k_gemm_dcn, cudaFuncAttributeMaxDynamicSharedMemorySize, DCN_SMEM);
        attr_done = true;
    }

    // ncu profiles launch idx 3 (0-based) -> keep k_gemm_fsm there
    k_pool<<<BB*CC, 256>>>(feat_l);
    k_atten<<<BB, CC>>>(w_atten);
    k_T_fsm2<<<128, 256>>>(w_fsm);
    k_gemm_fsm<<<dim3(HH, BB), 256>>>(feat_l);
    k_upsample<<<(BB*CC*HW)/256, 256>>>(feat_s);
    k_T_off<<<128, 256>>>(w_off);
    k_T_om<<<1152, 256>>>(w_offmask);
    k_T_dcn<<<576, 256>>>(w_dcn);
    k_gemm_off<<<dim3(HH, BB), 256>>>();
    k_gemm_om<<<dim3(HH, BB, 2), 256>>>(b_offmask);
    k_gemm_dcn<<<dim3(HH, BB), 256, DCN_SMEM>>>(feat_l, b_dcn, out);
}

// round 16
// speedup vs baseline: 1.6523x; 1.6523x over previous
#include <cuda_runtime.h>
#include <cuda_bf16.h>

#define BB 2
#define CC 128
#define HH 128
#define WWD 128
#define HW 16384
#define GG 8
#define CG 16
#define KK9 9
#define OMC 216
#define KDIM 1152
#define KC 16

typedef unsigned long long ull;
typedef unsigned short ushort;
typedef unsigned int uint;

// ---------------- static scratch ----------------
__device__ float g_feat_up [BB*CC*HW];
__device__ float g_feat_arm[BB*CC*HW];
__device__ float g_om      [BB*OMC*HW];
__device__ float g_pooled  [BB*CC];
__device__ float g_scale   [BB*CC];
__device__ float g_WT_fsm2 [BB*CC*CC];     // [b][c][o], scale folded
__device__ float g_WT_off  [2*CC*CC];      // [c][o], x2 folded for c>=128
__device__ float g_WT_dcn  [KDIM*CC];      // [(g*9+kk)*16+cg][o]
// pixel-major bf16 hi/lo offset_feat [b][y][x][c]
__device__ ushort g_offT_hi[(size_t)BB*HW*CC];
__device__ ushort g_offT_lo[(size_t)BB*HW*CC];
// om weights as pre-swizzled smem images: [tile2][chunk18][16KB tile]
__device__ ushort g_WA_hi[2*18*8192];
__device__ ushort g_WA_lo[2*18*8192];

// ---------------- scalar helpers ----------------
__device__ __forceinline__ ull ffma2(ull a, ull b, ull c){
    ull d;
    asm("fma.rn.f32x2 %0, %1, %2, %3;" : "=l"(d) : "l"(a), "l"(b), "l"(c));
    return d;
}
__device__ __forceinline__ ull splat2(float a){
    ull d;
    asm("mov.b64 %0, {%1, %1};" : "=l"(d) : "f"(a));
    return d;
}
__device__ __forceinline__ float2 unpack2(ull v){
    float2 r;
    asm("mov.b64 {%0, %1}, %2;" : "=f"(r.x), "=f"(r.y) : "l"(v));
    return r;
}
__device__ __forceinline__ int swz(int b){ return b ^ ((b >> 3) & 16); }

__device__ __forceinline__ unsigned su32(const void* p){
    return (unsigned)__cvta_generic_to_shared(p);
}
__device__ __forceinline__ void cp16(unsigned s, const void* g){
    asm volatile("cp.async.cg.shared.global [%0], [%1], 16;" :: "r"(s), "l"(g));
}
__device__ __forceinline__ void sts_zero16(unsigned a){
    asm volatile("st.shared.v4.b32 [%0], {%1,%1,%1,%1};" :: "r"(a), "r"(0) : "memory");
}
#define CP_COMMIT asm volatile("cp.async.commit_group;")
#define CP_WAIT0  asm volatile("cp.async.wait_group 0;")

// ---------------- mma.sync helpers (plain sm_103-safe) ----------------
__device__ __forceinline__ void ldsm4(uint* r, unsigned addr){
    asm volatile("ldmatrix.sync.aligned.m8n8.x4.shared.b16 {%0,%1,%2,%3}, [%4];"
        : "=r"(r[0]), "=r"(r[1]), "=r"(r[2]), "=r"(r[3]) : "r"(addr));
}
__device__ __forceinline__ void mma16816(float* d, const uint* a, const uint* b){
    asm volatile(
        "mma.sync.aligned.m16n8k16.row.col.f32.bf16.bf16.f32 "
        "{%0,%1,%2,%3}, {%4,%5,%6,%7}, {%8,%9}, {%0,%1,%2,%3};"
        : "+f"(d[0]), "+f"(d[1]), "+f"(d[2]), "+f"(d[3])
        : "r"(a[0]), "r"(a[1]), "r"(a[2]), "r"(a[3]), "r"(b[0]), "r"(b[1]));
}

// ---------------- scalar inner MMA (round-11) ----------------
__device__ __forceinline__ void mma_chunk(const char* __restrict__ Ws,
                                          const char* __restrict__ Xs,
                                          ull acc[8][4],
                                          int oA0, int oA1, int oB0, int oB1){
#pragma unroll
    for (int k = 0; k < KC; k++){
        ulonglong2 b01 = *reinterpret_cast<const ulonglong2*>(Xs + k*512 + oB0);
        ulonglong2 b23 = *reinterpret_cast<const ulonglong2*>(Xs + k*512 + oB1);
        float4 a0 = *reinterpret_cast<const float4*>(Ws + k*512 + oA0);
        float4 a1 = *reinterpret_cast<const float4*>(Ws + k*512 + oA1);
        float av[8] = {a0.x,a0.y,a0.z,a0.w,a1.x,a1.y,a1.z,a1.w};
#pragma unroll
        for (int j = 0; j < 8; j++){
            ull a2 = splat2(av[j]);
            acc[j][0] = ffma2(a2, b01.x, acc[j][0]);
            acc[j][1] = ffma2(a2, b01.y, acc[j][1]);
            acc[j][2] = ffma2(a2, b23.x, acc[j][2]);
            acc[j][3] = ffma2(a2, b23.y, acc[j][3]);
        }
    }
}

// ---------------- weight prep ----------------
__global__ void k_T_fsm2(const float* __restrict__ w){
    int i = blockIdx.x*256 + threadIdx.x;
    if (i < BB*CC*CC){
        int b = i >> 14, c = (i >> 7) & 127, o = i & 127;
        g_WT_fsm2[i] = w[o*CC + c] * g_scale[b*CC + c];
    }
}
__global__ void k_T_off(const float* __restrict__ w){    // w: [128][256]
    int i = blockIdx.x*256 + threadIdx.x;
    if (i < 2*CC*CC){
        int c = i >> 7, o = i & 127;
        float f = (c < CC) ? 1.f : 2.f;
        g_WT_off[i] = w[o*2*CC + c] * f;
    }
}
__global__ void k_T_dcn(const float* __restrict__ w){    // w: [128][128][3][3]
    int i = blockIdx.x*256 + threadIdx.x;
    if (i < KDIM*CC){
        int o = i & 127, kidx = i >> 7;
        int gk = kidx >> 4, cg = kidx & 15;
        int g = gk/9, kk = gk - g*9;
        int c = g*CG + cg;
        g_WT_dcn[i] = w[(o*CC + c)*KK9 + kk];
    }
}
// om weights -> pre-swizzled bf16 hi/lo smem images (SW128 atom layout)
__global__ void k_T_omtc(const float* __restrict__ w){   // w: [216][128][3][3]
    int i = blockIdx.x*256 + threadIdx.x;
    if (i >= 2*18*128*64) return;
    int kc = i & 63;
    int r1 = i >> 6;
    int o  = r1 & 127;
    int r2 = r1 >> 7;
    int chunk = r2 % 18, tile = r2 / 18;
    int tap = chunk >> 1, c0 = (chunk & 1)*64;
    int o_glob = tile*128 + o;
    int c = c0 + kc;
    float v = (o_glob < OMC) ? w[(o_glob*CC + c)*KK9 + tap] : 0.f;
    __nv_bfloat16 hb = __float2bfloat16(v);
    float hf = __bfloat162float(hb);
    __nv_bfloat16 lb = __float2bfloat16(v - hf);
    int off = (o & 7)*128 + kc*2;
    int sw  = off ^ ((o & 7) << 4);
    size_t byte = (size_t)(tile*18 + chunk)*16384 + (o >> 3)*1024 + sw;
    g_WA_hi[byte >> 1] = *reinterpret_cast<ushort*>(&hb);
    g_WA_lo[byte >> 1] = *reinterpret_cast<ushort*>(&lb);
}

// ---------------- pooled mean + attention scale ----------------
__global__ void k_pool(const float* __restrict__ fl){
    int bc = blockIdx.x, t = threadIdx.x;
    const float* p = fl + bc*HW;
    float s = 0.f;
    for (int i = t; i < HW; i += 256) s += p[i];
    __shared__ float red[256];
    red[t] = s; __syncthreads();
#pragma unroll
    for (int o = 128; o > 0; o >>= 1){
        if (t < o) red[t] += red[t + o];
        __syncthreads();
    }
    if (t == 0) g_pooled[bc] = red[0] * (1.f/(float)HW);
}
__global__ void k_atten(const float* __restrict__ w_atten){
    int b = blockIdx.x, o = threadIdx.x;
    __shared__ float pl[CC];
    pl[o] = g_pooled[b*CC + o];
    __syncthreads();
    float s = 0.f;
    const float* wr = w_atten + o*CC;
    for (int c = 0; c < CC; c++) s = fmaf(pl[c], wr[c], s);
    s = fmaxf(s, 0.f);
    g_scale[b*CC + o] = 1.f + 1.f/(1.f + __expf(-s));
}

// ---------------- bilinear upsample ----------------
__global__ void k_upsample(const float* __restrict__ fs){
    int idx = blockIdx.x*256 + threadIdx.x;
    int x = idx & 127, y = (idx >> 7) & 127, bc = idx >> 14;
    float fy = y*0.5f - 0.25f, fx = x*0.5f - 0.25f;
    float y0f = floorf(fy), x0f = floorf(fx);
    float wy = fy - y0f, wx = fx - x0f;
    int y0 = (int)y0f, x0 = (int)x0f;
    int y0c = max(y0, 0), y1c = min(y0 + 1, 63);
    int x0c = max(x0, 0), x1c = min(x0 + 1, 63);
    const float* s = fs + bc*4096;
    float v00 = s[y0c*64 + x0c], v01 = s[y0c*64 + x1c];
    float v10 = s[y1c*64 + x0c], v11 = s[y1c*64 + x1c];
    g_feat_up[idx] = (1.f-wy)*((1.f-wx)*v00 + wx*v01) + wy*((1.f-wx)*v10 + wx*v11);
}

// ---------------- GEMM 1: feat_arm = relu(Wfsm' @ feat_l) ----------------
__global__ __launch_bounds__(256,2) void k_gemm_fsm(const float* __restrict__ feat_l){
    __shared__ float Wsm[2][KC*128], Xsm[2][KC*128];
    int y = blockIdx.x, b = blockIdx.y, t = threadIdx.x;
    int to = t >> 4, tp = t & 15, r = to;
    int oB0 = swz(tp*32), oB1 = swz(tp*32 + 16);
    int oA0 = swz(to*32), oA1 = swz(to*32 + 16);
    ull acc[8][4];
#pragma unroll
    for (int j = 0; j < 8; j++) for (int i = 0; i < 4; i++) acc[j][i] = 0ull;

    const float* wbase = g_WT_fsm2 + b*CC*CC + r*128 + tp*8;
    const float* xbase = feat_l + ((b*CC + r)*HH + y)*WWD + tp*8;

    auto stage = [&](int c){
        int buf = c & 1;
        unsigned wd = su32((char*)Wsm[buf] + r*512);
        unsigned xd = su32((char*)Xsm[buf] + r*512);
        cp16(wd + oB0, wbase + c*KC*128);
        cp16(wd + oB1, wbase + c*KC*128 + 4);
        cp16(xd + oB0, xbase + c*KC*HW);
        cp16(xd + oB1, xbase + c*KC*HW + 4);
        CP_COMMIT;
    };
    stage(0);
#pragma unroll 1
    for (int c = 0; c < 8; c++){
        CP_WAIT0;
        __syncthreads();
        if (c < 7) stage(c+1);
        mma_chunk((char*)Wsm[c&1], (char*)Xsm[c&1], acc, oA0, oA1, oB0, oB1);
    }
#pragma unroll
    for (int j = 0; j < 8; j++){
        int o = to*8 + j;
        float2* dst = reinterpret_cast<float2*>(g_feat_arm + ((b*CC+o)*HH + y)*WWD + tp*8);
#pragma unroll
        for (int i2 = 0; i2 < 4; i2++){
            float2 v = unpack2(acc[j][i2]);
            v.x = fmaxf(v.x, 0.f); v.y = fmaxf(v.y, 0.f);
            dst[i2] = v;
        }
    }
}

// ---------------- GEMM 2: offset_feat -> pixel-major bf16 hi/lo -------------
__global__ __launch_bounds__(256,2) void k_gemm_off(){
    __shared__ float Wsm[2][KC*128], Xsm[2][KC*128];
    int y = blockIdx.x, b = blockIdx.y, t = threadIdx.x;
    int to = t >> 4, tp = t & 15, r = to;
    int oB0 = swz(tp*32), oB1 = swz(tp*32 + 16);
    int oA0 = swz(to*32), oA1 = swz(to*32 + 16);
    ull acc[8][4];
#pragma unroll
    for (int j = 0; j < 8; j++) for (int i = 0; i < 4; i++) acc[j][i] = 0ull;

    const float* wbase = g_WT_off + r*128 + tp*8;
    auto stage = [&](int c){
        int buf = c & 1;
        unsigned wd = su32((char*)Wsm[buf] + r*512);
        unsigned xd = su32((char*)Xsm[buf] + r*512);
        cp16(wd + oB0, wbase + c*KC*128);
        cp16(wd + oB1, wbase + c*KC*128 + 4);
        int ch = c*KC + r;
        const float* xp = (ch < CC) ? g_feat_arm + ((b*CC + ch)*HH + y)*WWD + tp*8
                                    : g_feat_up  + ((b*CC + ch - CC)*HH + y)*WWD + tp*8;
        cp16(xd + oB0, xp);
        cp16(xd + oB1, xp + 4);
        CP_COMMIT;
    };
    stage(0);
#pragma unroll 1
    for (int c = 0; c < 16; c++){
        CP_WAIT0;
        __syncthreads();
        if (c < 15) stage(c+1);
        mma_chunk((char*)Wsm[c&1], (char*)Xsm[c&1], acc, oA0, oA1, oB0, oB1);
    }
    // epilogue: relu, split to bf16 hi/lo, transpose 8x8, write pixel-major
    float fv[8][8];
#pragma unroll
    for (int j = 0; j < 8; j++)
#pragma unroll
        for (int i2 = 0; i2 < 4; i2++){
            float2 v = unpack2(acc[j][i2]);
            fv[j][2*i2]   = fmaxf(v.x, 0.f);
            fv[j][2*i2+1] = fmaxf(v.y, 0.f);
        }
#pragma unroll
    for (int i = 0; i < 8; i++){
        uint hp[4], lp[4];
#pragma unroll
        for (int jp = 0; jp < 4; jp++){
            float v0 = fv[2*jp][i], v1 = fv[2*jp+1][i];
            __nv_bfloat16 h0 = __float2bfloat16(v0);
            __nv_bfloat16 h1 = __float2bfloat16(v1);
            __nv_bfloat16 l0 = __float2bfloat16(v0 - __bfloat162float(h0));
            __nv_bfloat16 l1 = __float2bfloat16(v1 - __bfloat162float(h1));
            hp[jp] = (uint)*reinterpret_cast<ushort*>(&h0) |
                     ((uint)*reinterpret_cast<ushort*>(&h1) << 16);
            lp[jp] = (uint)*reinterpret_cast<ushort*>(&l0) |
                     ((uint)*reinterpret_cast<ushort*>(&l1) << 16);
        }
        int px = tp*8 + i;
        size_t base = ((size_t)((b*HH + y)*WWD + px))*CC + to*8;
        *reinterpret_cast<uint4*>(g_offT_hi + base) = make_uint4(hp[0],hp[1],hp[2],hp[3]);
        *reinterpret_cast<uint4*>(g_offT_lo + base) = make_uint4(lp[0],lp[1],lp[2],lp[3]);
    }
}

// ---------------- GEMM 3: conv_offset_mask via mma.sync bf16-split ----------
// dyn smem (1KB-aligned): Ah[2][16K] Al[2][16K] Bh[2][16K] Bl[2][16K]
#define OM_SMEM (131072 + 1024)
__global__ void k_gemm_om_mma(const float* __restrict__ b_offmask){
    extern __shared__ char dyn[];
    int t = threadIdx.x, wid = t >> 5, lane = t & 31;
    int y = blockIdx.x, b = blockIdx.y, oz = blockIdx.z;
    int wo = wid >> 1, wp = wid & 1;          // warp tile: 32o x 64p
    unsigned ub = (su32(dyn) + 1023u) & ~1023u;

    auto Ah = [&](int buf){ return ub + (unsigned)buf*16384u; };
    auto Al = [&](int buf){ return ub + 32768u + (unsigned)buf*16384u; };
    auto Bh = [&](int buf){ return ub + 65536u + (unsigned)buf*16384u; };
    auto Bl = [&](int buf){ return ub + 98304u + (unsigned)buf*16384u; };

    float acc[2][8][4];
#pragma unroll
    for (int ot = 0; ot < 2; ot++)
        for (int g = 0; g < 8; g++)
            for (int q = 0; q < 4; q++) acc[ot][g][q] = 0.f;

    auto stage = [&](int c){
        int buf = c & 1;
        // A: linear copy of pre-swizzled image (64B/thread each hi,lo)
        {
            size_t so = (size_t)(oz*18 + c)*8192 + (size_t)t*32;   // ushort units
            const char* sh = (const char*)(g_WA_hi + so);
            const char* sl = (const char*)(g_WA_lo + so);
            unsigned dh = Ah(buf) + (unsigned)t*64;
            unsigned dl = Al(buf) + (unsigned)t*64;
#pragma unroll
            for (int q = 0; q < 4; q++){
                cp16(dh + q*16, sh + q*16);
                cp16(dl + q*16, sl + q*16);
            }
        }
        // B: 128 p-rows x 128B (64 c bf16), hi/lo; halo-shifted gather
        {
            int row = t >> 1, which = t & 1;
            int tap = c >> 1, c0 = (c & 1)*64;
            int ty = tap/3 - 1, tx = tap - (tap/3)*3 - 1;
            int pys = y + ty, pxs = row + tx;
            unsigned dB = (which ? Bl(buf) : Bh(buf))
                          + (unsigned)((row>>3)*1024 + (row&7)*128);
            int xr = (row & 7) << 4;
            if (pys >= 0 && pys < HH && pxs >= 0 && pxs < WWD){
                const ushort* sp = (which ? g_offT_lo : g_offT_hi)
                                   + ((size_t)((b*HH + pys)*WWD + pxs))*CC + c0;
#pragma unroll
                for (int q = 0; q < 8; q++)
                    cp16(dB + ((q*16) ^ xr), (const char*)sp + q*16);
            } else {
#pragma unroll
                for (int q = 0; q < 8; q++)
                    sts_zero16(dB + ((q*16) ^ xr));
            }
        }
        CP_COMMIT;
    };

    int lo16 = lane & 15, lsub = lane >> 4;            // A ldmatrix lanes
    int brow = ((lane >> 4) << 3) + (lane & 7);        // B ldmatrix: row within 16
    int bks  = (lane >> 3) & 1;                        // B ldmatrix: k-half

    auto compute = [&](int buf){
        unsigned AhB = Ah(buf), AlB = Al(buf), BhB = Bh(buf), BlB = Bl(buf);
#pragma unroll
        for (int ks = 0; ks < 4; ks++){
            uint ah[2][4], al[2][4];
#pragma unroll
            for (int ot = 0; ot < 2; ot++){
                int o = wo*32 + ot*16 + lo16;
                unsigned off = (unsigned)((o>>3)*1024 + (o&7)*128
                               + ((ks*32 + lsub*16) ^ ((o&7)<<4)));
                ldsm4(ah[ot], AhB + off);
                ldsm4(al[ot], AlB + off);
            }
#pragma unroll
            for (int g = 0; g < 4; g++){
                int n = wp*64 + g*16 + brow;
                unsigned off = (unsigned)((n>>3)*1024 + (n&7)*128
                               + ((ks*32 + bks*16) ^ ((n&7)<<4)));
                uint bh[4], bl[4];
                ldsm4(bh, BhB + off);
                ldsm4(bl, BlB + off);
#pragma unroll
                for (int ot = 0; ot < 2; ot++){
                    mma16816(acc[ot][2*g],   ah[ot], bh);
                    mma16816(acc[ot][2*g],   al[ot], bh);
                    mma16816(acc[ot][2*g],   ah[ot], bl);
                    mma16816(acc[ot][2*g+1], ah[ot], bh+2);
                    mma16816(acc[ot][2*g+1], al[ot], bh+2);
                    mma16816(acc[ot][2*g+1], ah[ot], bl+2);
                }
            }
        }
    };

    stage(0);
#pragma unroll 1
    for (int c = 0; c < 18; c++){
        CP_WAIT0;
        __syncthreads();
        if (c < 17) stage(c+1);
        compute(c & 1);
    }

    // epilogue: bias add, write g_om[(b,o)][y*128+p]
    int rr = lane >> 2, cp2 = (lane & 3)*2;
#pragma unroll
    for (int ot = 0; ot < 2; ot++){
#pragma unroll
        for (int g = 0; g < 8; g++){
            int p = wp*64 + g*8 + cp2;
#pragma unroll
            for (int half = 0; half < 2; half++){
                int o = oz*128 + wo*32 + ot*16 + rr + half*8;
                if (o < OMC){
                    float bias = b_offmask[o];
                    float2 v;
                    v.x = acc[ot][g][2*half]   + bias;
                    v.y = acc[ot][g][2*half+1] + bias;
                    *reinterpret_cast<float2*>(
                        g_om + ((size_t)(b*OMC + o))*HW + y*WWD + p) = v;
                }
            }
        }
    }
}

// ---------------- GEMM 4: modulated deformable conv (scalar) ----------------
__global__ __launch_bounds__(256,2) void k_gemm_dcn(const float* __restrict__ feat_l,
                                                    const float* __restrict__ b_dcn,
                                                    float* __restrict__ out){
    __shared__ float Wsm[2][KC*128], Xsm[2][KC*128];
    __shared__ float4 swt[2][128];
    __shared__ int4  sof[2][128];
    int y = blockIdx.x, b = blockIdx.y, t = threadIdx.x;
    int to = t >> 4, tp = t & 15, r = to;
    int oB0 = swz(tp*32), oB1 = swz(tp*32 + 16);
    int oA0 = swz(to*32), oA1 = swz(to*32 + 16);
    ull acc[8][4];
#pragma unroll
    for (int j = 0; j < 8; j++) for (int i = 0; i < 4; i++) acc[j][i] = 0ull;

    int xs_self = t ^ ((t >> 3) & 7);
    const float* omp = g_om + (size_t)b*OMC*HW + y*WWD + (t & 127);

    float rom0 = 0.f, rom1 = 0.f, rom2 = 0.f;
    auto load_rom = [&](int m){
        int g = m/9, kk = m - 9*g;
        rom0 = omp[(size_t)(g*18 + kk*2    )*HW];
        rom1 = omp[(size_t)(g*18 + kk*2 + 1)*HW];
        rom2 = omp[(size_t)(144 + g*9 + kk )*HW];
    };
    auto calc_params = [&](int m, int pbuf){
        int kk = m - 9*(m/9);
        int x = t;
        float mval = 1.f/(1.f + __expf(-rom2));
        float py = (float)(y + kk/3 - 1) + rom0;
        float px = (float)(x + (kk - (kk/3)*3) - 1) + rom1;
        float y0f = floorf(py), x0f = floorf(px);
        float ly = py - y0f, lx = px - x0f;
        int y0 = (int)y0f, x0 = (int)x0f;
        float vy0 = (y0 >=  0 && y0 < HH    ) ? 1.f : 0.f;
        float vy1 = (y0 >= -1 && y0 < HH - 1) ? 1.f : 0.f;
        float vx0 = (x0 >=  0 && x0 < WWD    ) ? 1.f : 0.f;
        float vx1 = (x0 >= -1 && x0 < WWD - 1) ? 1.f : 0.f;
        float omy = 1.f - ly, omx = 1.f - lx;
        float4 w;
        w.x = omy*omx*vy0*vx0*mval;
        w.y = omy*lx *vy0*vx1*mval;
        w.z = ly *omx*vy1*vx0*mval;
        w.w = ly *lx *vy1*vx1*mval;
        int y0c = min(max(y0,0),HH-1),   y1c = min(max(y0+1,0),HH-1);
        int x0c = min(max(x0,0),WWD-1),  x1c = min(max(x0+1,0),WWD-1);
        sof[pbuf][xs_self] = make_int4(y0c*WWD + x0c, y0c*WWD + x1c,
                                       y1c*WWD + x0c, y1c*WWD + x1c);
        swt[pbuf][xs_self] = w;
    };
    auto stW = [&](int m){
        int buf = m & 1;
        unsigned wd = su32((char*)Wsm[buf] + r*512);
        const float* wp = g_WT_dcn + (m*16 + r)*128 + tp*8;
        cp16(wd + oB0, wp);
        cp16(wd + oB1, wp + 4);
        CP_COMMIT;
    };
    float rx[8];
    auto gather = [&](int m, int pbuf){
        int g = m/9;
        const float* fp = g_feat_up + (size_t)(b*CC + g*CG + r)*HW;
#pragma unroll
        for (int i = 0; i < 8; i++){
            int px = tp*8 + i;
            int pidx = px ^ ((px >> 3) & 7);
            int4  o4 = sof[pbuf][pidx];
            float4 w4 = swt[pbuf][pidx];
            rx[i] = w4.x*fp[o4.x] + w4.y*fp[o4.y] + w4.z*fp[o4.z] + w4.w*fp[o4.w];
        }
    };

    if (t < 128){
        load_rom(0);
        calc_params(0, 0);
        load_rom(1);
    }
    stW(0);
    __syncthreads();
    gather(0, 0);

#pragma unroll 1
    for (int c = 0; c < 72; c++){
        int buf = c & 1;
        char* X = (char*)Xsm[buf] + r*512;
        *(float4*)(X + oB0) = make_float4(rx[0], rx[1], rx[2], rx[3]);
        *(float4*)(X + oB1) = make_float4(rx[4], rx[5], rx[6], rx[7]);
        CP_WAIT0;
        __syncthreads();
        if (c + 1 < 72){
            stW(c+1);
            if (t < 128) calc_params(c+1, (c+1) & 1);
            if (t < 128 && c + 2 < 72) load_rom(c+2);
        }
        __syncthreads();
        if (c + 1 < 72) gather(c+1, (c+1) & 1);
        mma_chunk((char*)Wsm[buf], (char*)Xsm[buf], acc, oA0, oA1, oB0, oB1);
    }

#pragma unroll
    for (int j = 0; j < 8; j++){
        int o = to*8 + j;
        float bias = b_dcn[o];
        int base = ((b*CC + o)*HH + y)*WWD + tp*8;
        const float2* flp = reinterpret_cast<const float2*>(feat_l + base);
        float2* dst = reinterpret_cast<float2*>(out + base);
#pragma unroll
        for (int i2 = 0; i2 < 4; i2++){
            float2 v  = unpack2(acc[j][i2]);
            float2 fl = flp[i2];
            v.x = fmaxf(v.x + bias, 0.f) + fl.x;
            v.y = fmaxf(v.y + bias, 0.f) + fl.y;
            dst[i2] = v;
        }
    }
}

// ---------------- launcher ----------------
extern "C" void kernel_launch(void* const* d_in, const int* in_sizes, int n_in,
                              void* d_out, int out_size){
    (void)in_sizes; (void)n_in; (void)out_size;
    const float* feat_l    = (const float*)d_in[0];
    const float* feat_s    = (const float*)d_in[1];
    const float* w_atten   = (const float*)d_in[2];
    const float* w_fsm     = (const float*)d_in[3];
    const float* w_off     = (const float*)d_in[4];
    const float* w_offmask = (const float*)d_in[5];
    const float* b_offmask = (const float*)d_in[6];
    const float* w_dcn     = (const float*)d_in[7];
    const float* b_dcn     = (const float*)d_in[8];
    float* out = (float*)d_out;

    static bool attr_done = false;
    if (!attr_done){
        cudaFuncSetAttribute(k_gemm_om_mma, cudaFuncAttributeMaxDynamicSharedMemorySize, OM_SMEM);
        attr_done = true;
    }

    // ncu profiles launch idx 3 (0-based) -> keep k_gemm_fsm there
    k_pool<<<BB*CC, 256>>>(feat_l);
    k_atten<<<BB, CC>>>(w_atten);
    k_T_fsm2<<<128, 256>>>(w_fsm);
    k_gemm_fsm<<<dim3(HH, BB), 256>>>(feat_l);
    k_upsample<<<(BB*CC*HW)/256, 256>>>(feat_s);
    k_T_off<<<128, 256>>>(w_off);
    k_T_omtc<<<1152, 256>>>(w_offmask);
    k_T_dcn<<<576, 256>>>(w_dcn);
    k_gemm_off<<<dim3(HH, BB), 256>>>();
    k_gemm_om_mma<<<dim3(HH, BB, 2), 256, OM_SMEM>>>(b_offmask);
    k_gemm_dcn<<<dim3(HH, BB), 256>>>(feat_l, b_dcn, out);
}